// round 1
// baseline (speedup 1.0000x reference)
#include <cuda_runtime.h>

// Problem constants
#define Bn 8
#define Tn 256
#define Un 64
#define Hn 512
#define Fn 1024

// Scratch for intermediate projections (no cudaMalloc allowed)
__device__ float g_a[Bn * Tn * Fn];   // 8 MB: audio @ Wa + bias
__device__ float g_l[Bn * Un * Fn];   // 2 MB: label @ Wl

// ---------------------------------------------------------------------------
// Kernel 1: fused SGEMM for both projections.
// Logical A: rows 0..2047 = audio (B*T, H), rows 2048..2559 = label (B*U, H).
// BM=128 => block rows 0..15 are pure audio, 16..19 pure label.
// C = A @ W_slice (+ bias for audio rows).
// BM=128, BN=128, BK=16, 256 threads, 8x8 per-thread micro-tile.
// ---------------------------------------------------------------------------
__global__ __launch_bounds__(256, 1)
void joint_gemm_kernel(const float* __restrict__ audio,
                       const float* __restrict__ label,
                       const float* __restrict__ W,
                       const float* __restrict__ bias)
{
    const int br = blockIdx.y;          // 0..19
    const int bc = blockIdx.x;          // 0..7
    const bool is_audio = (br < 16);

    const float* Abase = is_audio ? (audio + (size_t)br * 128 * Hn)
                                  : (label + (size_t)(br - 16) * 128 * Hn);
    const float* Wbase = W + (is_audio ? 0 : (size_t)Hn * Fn);
    float* Cbase = is_audio ? (g_a + (size_t)br * 128 * Fn)
                            : (g_l + (size_t)(br - 16) * 128 * Fn);

    __shared__ float As[16][132];   // transposed A tile, padded
    __shared__ float Bs[16][132];   // W tile, padded (rows stay 16B aligned)

    const int tid = threadIdx.x;
    const int tx = tid & 15;        // 0..15 -> col group
    const int ty = tid >> 4;        // 0..15 -> row group
    const int row0 = ty * 8;
    const int col0 = tx * 8;

    float acc[8][8];
#pragma unroll
    for (int i = 0; i < 8; i++)
#pragma unroll
        for (int j = 0; j < 8; j++) acc[i][j] = 0.0f;

    for (int kt = 0; kt < Hn; kt += 16) {
        // Load A tile: 128 rows x 16 K. 512 float4 total, 2 per thread.
#pragma unroll
        for (int i = 0; i < 2; i++) {
            int id = tid + i * 256;           // 0..511
            int arow = id >> 2;               // 0..127
            int acol = id & 3;                // float4 index along K
            float4 v = *(const float4*)(Abase + (size_t)arow * Hn + kt + acol * 4);
            As[acol * 4 + 0][arow] = v.x;
            As[acol * 4 + 1][arow] = v.y;
            As[acol * 4 + 2][arow] = v.z;
            As[acol * 4 + 3][arow] = v.w;
        }
        // Load W tile: 16 K x 128 N. 512 float4 total, 2 per thread.
#pragma unroll
        for (int i = 0; i < 2; i++) {
            int id = tid + i * 256;
            int brow = id >> 5;               // 0..15
            int bcol = id & 31;               // float4 index along N
            float4 v = *(const float4*)(Wbase + (size_t)(kt + brow) * Fn + bc * 128 + bcol * 4);
            *(float4*)(&Bs[brow][bcol * 4]) = v;
        }
        __syncthreads();

#pragma unroll
        for (int k = 0; k < 16; k++) {
            float aR[8], bR[8];
            float4 a0 = *(const float4*)(&As[k][row0]);
            float4 a1 = *(const float4*)(&As[k][row0 + 4]);
            float4 b0 = *(const float4*)(&Bs[k][col0]);
            float4 b1 = *(const float4*)(&Bs[k][col0 + 4]);
            aR[0]=a0.x; aR[1]=a0.y; aR[2]=a0.z; aR[3]=a0.w;
            aR[4]=a1.x; aR[5]=a1.y; aR[6]=a1.z; aR[7]=a1.w;
            bR[0]=b0.x; bR[1]=b0.y; bR[2]=b0.z; bR[3]=b0.w;
            bR[4]=b1.x; bR[5]=b1.y; bR[6]=b1.z; bR[7]=b1.w;
#pragma unroll
            for (int i = 0; i < 8; i++)
#pragma unroll
                for (int j = 0; j < 8; j++)
                    acc[i][j] = fmaf(aR[i], bR[j], acc[i][j]);
        }
        __syncthreads();
    }

    // Epilogue: add bias for audio rows, write out with float4.
    float bv[8];
#pragma unroll
    for (int j = 0; j < 8; j++)
        bv[j] = is_audio ? bias[bc * 128 + col0 + j] : 0.0f;

#pragma unroll
    for (int i = 0; i < 8; i++) {
        float4 v0, v1;
        v0.x = acc[i][0] + bv[0]; v0.y = acc[i][1] + bv[1];
        v0.z = acc[i][2] + bv[2]; v0.w = acc[i][3] + bv[3];
        v1.x = acc[i][4] + bv[4]; v1.y = acc[i][5] + bv[5];
        v1.z = acc[i][6] + bv[6]; v1.w = acc[i][7] + bv[7];
        float* crow = Cbase + (size_t)(row0 + i) * Fn + bc * 128 + col0;
        *(float4*)(crow)     = v0;
        *(float4*)(crow + 4) = v1;
    }
}

// ---------------------------------------------------------------------------
// Kernel 2: broadcast add. out[b,t,u,f] = a[b,t,f] + l[b,u,f].
// CTA tile: 8 t x 64 u x 128 f. SMEM-staged a (4KB) and l (32KB).
// Each CTA writes 256 KB; pure HBM-write-bound.
// ---------------------------------------------------------------------------
__global__ __launch_bounds__(256, 4)
void joint_bcast_kernel(float* __restrict__ out)
{
    const int fb = blockIdx.x;    // 0..7  -> f tile of 128
    const int tb = blockIdx.y;    // 0..31 -> t tile of 8
    const int b  = blockIdx.z;    // 0..7

    __shared__ float sa[8][128];
    __shared__ float sl[64][128];

    const int tid = threadIdx.x;

    // Load a tile: 8 rows x 128 f = 256 float4, 1 per thread.
    {
        int r = tid >> 5, c = tid & 31;
        const float4* src = (const float4*)(g_a + ((size_t)(b * Tn + tb * 8 + r) * Fn) + fb * 128);
        ((float4*)sa[r])[c] = src[c];
    }
    // Load l tile: 64 rows x 128 f = 2048 float4, 8 per thread.
#pragma unroll
    for (int i = 0; i < 8; i++) {
        int id = tid + i * 256;
        int r = id >> 5, c = id & 31;
        const float4* src = (const float4*)(g_l + ((size_t)(b * Un + r) * Fn) + fb * 128);
        ((float4*)sl[r])[c] = src[c];
    }
    __syncthreads();

    const int r = tid >> 5;       // warp id: row-within-group
    const int c = tid & 31;       // float4 lane within the 128-f row
    const size_t bt0 = (size_t)b * Tn + (size_t)tb * 8;   // first global t-row
    float4* out4 = (float4*)out;
    const size_t base = bt0 * Un * (Fn / 4) + (size_t)fb * 32 + c;

    // 512 (t,u) rows per CTA, 8 rows (one per warp) per iteration.
#pragma unroll 4
    for (int it = 0; it < 64; it++) {
        int rowLocal = it * 8 + r;          // 0..511
        int t = rowLocal >> 6;              // 0..7
        int u = rowLocal & 63;              // 0..63
        float4 va = ((const float4*)sa[t])[c];
        float4 vl = ((const float4*)sl[u])[c];
        float4 v;
        v.x = va.x + vl.x; v.y = va.y + vl.y;
        v.z = va.z + vl.z; v.w = va.w + vl.w;
        out4[base + (size_t)rowLocal * (Fn / 4)] = v;
    }
}

// ---------------------------------------------------------------------------
extern "C" void kernel_launch(void* const* d_in, const int* in_sizes, int n_in,
                              void* d_out, int out_size)
{
    const float* audio = (const float*)d_in[0];   // (8,256,512)
    const float* label = (const float*)d_in[1];   // (8,64,512)
    const float* W     = (const float*)d_in[2];   // (1024,1024)
    const float* bias  = (const float*)d_in[3];   // (1024,)
    float* out = (float*)d_out;                   // (8,256,64,1024)

    dim3 ggrid(Fn / 128, (Bn * Tn + Bn * Un) / 128);   // (8, 20)
    joint_gemm_kernel<<<ggrid, 256>>>(audio, label, W, bias);

    dim3 bgrid(Fn / 128, Tn / 8, Bn);                  // (8, 32, 8)
    joint_bcast_kernel<<<bgrid, 256>>>(out);
}

// round 3
// speedup vs baseline: 1.7040x; 1.7040x over previous
#include <cuda_runtime.h>
#include <cstdint>

// Problem constants
#define Bn 8
#define Tn 256
#define Un 64
#define Hn 512
#define Fn 1024

// Scratch for intermediate projections (no cudaMalloc allowed)
__device__ float g_a[Bn * Tn * Fn];   // 8 MB: audio @ Wa + bias
__device__ float g_l[Bn * Un * Fn];   // 2 MB: label @ Wl

__device__ __forceinline__ float to_tf32(float x) {
    float r;
    asm("cvt.rna.tf32.f32 %0, %1;" : "=f"(r) : "f"(x));
    return r;
}

// ---------------------------------------------------------------------------
// Kernel 1: fused tf32 tensor-core GEMM for both projections.
// Logical A: rows 0..2047 = audio (B*T, H), rows 2048..2559 = label (B*U, H).
// BM=128 => block rows 0..15 pure audio, 16..19 pure label.
// C = A @ W_slice (+ bias for audio rows).
// BM=128, BN=128, BK=32, 256 threads, warp grid 2(M)x4(N), warp tile 64x32.
// mma.sync.aligned.m16n8k8.row.col.f32.tf32.tf32.f32
// ---------------------------------------------------------------------------
__global__ __launch_bounds__(256, 2)
void joint_gemm_tc(const float* __restrict__ audio,
                   const float* __restrict__ label,
                   const float* __restrict__ W,
                   const float* __restrict__ bias)
{
    const int br = blockIdx.y;          // 0..19
    const int bc = blockIdx.x;          // 0..7
    const bool is_audio = (br < 16);

    const float* Abase = is_audio ? (audio + (size_t)br * 128 * Hn)
                                  : (label + (size_t)(br - 16) * 128 * Hn);
    const float* Wbase = W + (is_audio ? 0 : (size_t)Hn * Fn) + bc * 128;
    float* Cbase = is_audio ? (g_a + (size_t)br * 128 * Fn + bc * 128)
                            : (g_l + (size_t)(br - 16) * 128 * Fn + bc * 128);

    // Padded for conflict-free frag loads:
    //  As frag-load bank = (36r + k) % 32 = (4g + tig + const) -> 32 distinct
    //  Bs frag-load bank = (136k + n) % 32 = (8tig + g + const) -> distinct
    __shared__ float As[128][36];
    __shared__ float Bs[32][136];

    const int tid = threadIdx.x;
    const int warp = tid >> 5;
    const int lane = tid & 31;
    const int warpM = warp >> 2;        // 0..1
    const int warpN = warp & 3;         // 0..3
    const int g = lane >> 2;            // 0..7
    const int tig = lane & 3;           // 0..3

    float c[4][4][4];
#pragma unroll
    for (int mt = 0; mt < 4; mt++)
#pragma unroll
        for (int nt = 0; nt < 4; nt++)
#pragma unroll
            for (int r = 0; r < 4; r++) c[mt][nt][r] = 0.0f;

    for (int kt = 0; kt < Hn; kt += 32) {
        // Load A tile: 128 rows x 32 K = 1024 float4, 4 per thread.
#pragma unroll
        for (int i = 0; i < 4; i++) {
            int id = tid + i * 256;
            int r = id >> 3;            // 0..127
            int c4 = id & 7;            // float4 along K
            float4 v = *(const float4*)(Abase + (size_t)r * Hn + kt + c4 * 4);
            float* dst = &As[r][c4 * 4];
            dst[0] = to_tf32(v.x); dst[1] = to_tf32(v.y);
            dst[2] = to_tf32(v.z); dst[3] = to_tf32(v.w);
        }
        // Load W tile: 32 K x 128 N = 1024 float4, 4 per thread.
#pragma unroll
        for (int i = 0; i < 4; i++) {
            int id = tid + i * 256;
            int kr = id >> 5;           // 0..31
            int c4 = id & 31;           // float4 along N
            float4 v = *(const float4*)(Wbase + (size_t)(kt + kr) * Fn + c4 * 4);
            float* dst = &Bs[kr][c4 * 4];
            dst[0] = to_tf32(v.x); dst[1] = to_tf32(v.y);
            dst[2] = to_tf32(v.z); dst[3] = to_tf32(v.w);
        }
        __syncthreads();

#pragma unroll
        for (int ks = 0; ks < 4; ks++) {
            uint32_t af[4][4], bf[4][2];
#pragma unroll
            for (int mt = 0; mt < 4; mt++) {
                int r0 = warpM * 64 + mt * 16 + g;
                int k0 = ks * 8 + tig;
                af[mt][0] = __float_as_uint(As[r0][k0]);
                af[mt][1] = __float_as_uint(As[r0 + 8][k0]);
                af[mt][2] = __float_as_uint(As[r0][k0 + 4]);
                af[mt][3] = __float_as_uint(As[r0 + 8][k0 + 4]);
            }
#pragma unroll
            for (int nt = 0; nt < 4; nt++) {
                int n0 = warpN * 32 + nt * 8 + g;
                bf[nt][0] = __float_as_uint(Bs[ks * 8 + tig][n0]);
                bf[nt][1] = __float_as_uint(Bs[ks * 8 + tig + 4][n0]);
            }
#pragma unroll
            for (int mt = 0; mt < 4; mt++)
#pragma unroll
                for (int nt = 0; nt < 4; nt++) {
                    asm volatile(
                        "mma.sync.aligned.m16n8k8.row.col.f32.tf32.tf32.f32 "
                        "{%0,%1,%2,%3}, {%4,%5,%6,%7}, {%8,%9}, {%0,%1,%2,%3};"
                        : "+f"(c[mt][nt][0]), "+f"(c[mt][nt][1]),
                          "+f"(c[mt][nt][2]), "+f"(c[mt][nt][3])
                        : "r"(af[mt][0]), "r"(af[mt][1]),
                          "r"(af[mt][2]), "r"(af[mt][3]),
                          "r"(bf[nt][0]), "r"(bf[nt][1]));
                }
        }
        __syncthreads();
    }

    // Epilogue: thread owns C[row(+8)][col, col+1] per (mt, nt) tile.
#pragma unroll
    for (int nt = 0; nt < 4; nt++) {
        int col = warpN * 32 + nt * 8 + 2 * tig;
        float b0 = 0.0f, b1 = 0.0f;
        if (is_audio) {
            b0 = bias[bc * 128 + col];
            b1 = bias[bc * 128 + col + 1];
        }
#pragma unroll
        for (int mt = 0; mt < 4; mt++) {
            int row = warpM * 64 + mt * 16 + g;
            float2 v0, v1;
            v0.x = c[mt][nt][0] + b0; v0.y = c[mt][nt][1] + b1;
            v1.x = c[mt][nt][2] + b0; v1.y = c[mt][nt][3] + b1;
            *(float2*)(Cbase + (size_t)row * Fn + col) = v0;
            *(float2*)(Cbase + (size_t)(row + 8) * Fn + col) = v1;
        }
    }
}

// ---------------------------------------------------------------------------
// Kernel 2: broadcast add. out[b,t,u,f] = a[b,t,f] + l[b,u,f].
// CTA tile: 8 t x 64 u x 128 f. SMEM-staged a (4KB) and l (32KB).
// Each CTA writes 256 KB; pure HBM-write-bound. Streaming stores (.cs) —
// output is 512 MB with zero reuse, keep it out of L2 as much as possible.
// ---------------------------------------------------------------------------
__global__ __launch_bounds__(256, 4)
void joint_bcast_kernel(float* __restrict__ out)
{
    const int fb = blockIdx.x;    // 0..7  -> f tile of 128
    const int tb = blockIdx.y;    // 0..31 -> t tile of 8
    const int b  = blockIdx.z;    // 0..7

    __shared__ float sa[8][128];
    __shared__ float sl[64][128];

    const int tid = threadIdx.x;

    // Load a tile: 8 rows x 128 f = 256 float4, 1 per thread.
    {
        int r = tid >> 5, c = tid & 31;
        const float4* src = (const float4*)(g_a + ((size_t)(b * Tn + tb * 8 + r) * Fn) + fb * 128);
        ((float4*)sa[r])[c] = src[c];
    }
    // Load l tile: 64 rows x 128 f = 2048 float4, 8 per thread.
#pragma unroll
    for (int i = 0; i < 8; i++) {
        int id = tid + i * 256;
        int r = id >> 5, c = id & 31;
        const float4* src = (const float4*)(g_l + ((size_t)(b * Un + r) * Fn) + fb * 128);
        ((float4*)sl[r])[c] = src[c];
    }
    __syncthreads();

    const int r = tid >> 5;       // warp id: row-within-group
    const int c = tid & 31;       // float4 lane within the 128-f row
    const size_t bt0 = (size_t)b * Tn + (size_t)tb * 8;   // first global t-row
    float4* out4 = (float4*)out;
    const size_t base = bt0 * Un * (Fn / 4) + (size_t)fb * 32 + c;

    // 512 (t,u) rows per CTA, 8 rows (one per warp) per iteration.
#pragma unroll 4
    for (int it = 0; it < 64; it++) {
        int rowLocal = it * 8 + r;          // 0..511
        int t = rowLocal >> 6;              // 0..7
        int u = rowLocal & 63;              // 0..63
        float4 va = ((const float4*)sa[t])[c];
        float4 vl = ((const float4*)sl[u])[c];
        float4 v;
        v.x = va.x + vl.x; v.y = va.y + vl.y;
        v.z = va.z + vl.z; v.w = va.w + vl.w;
        __stcs(&out4[base + (size_t)rowLocal * (Fn / 4)], v);
    }
}

// ---------------------------------------------------------------------------
extern "C" void kernel_launch(void* const* d_in, const int* in_sizes, int n_in,
                              void* d_out, int out_size)
{
    const float* audio = (const float*)d_in[0];   // (8,256,512)
    const float* label = (const float*)d_in[1];   // (8,64,512)
    const float* W     = (const float*)d_in[2];   // (1024,1024)
    const float* bias  = (const float*)d_in[3];   // (1024,)
    float* out = (float*)d_out;                   // (8,256,64,1024)

    dim3 ggrid(Fn / 128, (Bn * Tn + Bn * Un) / 128);   // (8, 20)
    joint_gemm_tc<<<ggrid, 256>>>(audio, label, W, bias);

    dim3 bgrid(Fn / 128, Tn / 8, Bn);                  // (8, 32, 8)
    joint_bcast_kernel<<<bgrid, 256>>>(out);
}